// round 16
// baseline (speedup 1.0000x reference)
#include <cuda_runtime.h>
#include <cstdint>

// Forward 5/3 lifting wavelet, 2D separable, fused tile kernel.
// x: (8, 32, 512, 512) f32 -> out: (8, 128, 256, 256) f32
// out channels: [LL(0:32) | LH(32:64) | HL(64:96) | HH(96:128)]
//
//   d[i] = odd[i] - 0.5*(even[il] + even[ir]), il=(i==0)?1:i-1, ir=(i==255)?254:i+1
//   s[i] = even[i] + 0.25*(d[il] + d[ir])     (same reflected indices)
//
// R=4 rows/strip (15-row tile, 30KB smem), 256-thread CTAs, 4 CTAs/SM:
// half-length phases double the temporal R/W interleave granularity at the
// DRAM controller vs R=8, with the same proven occupancy/register shape.
// Phase A: software-pipelined LDG + rotation shuffles. Phase B: interior
// strips fully unrolled (6 iterations, compile-time predicates).

static constexpr int H = 512;
static constexpr int Wd = 512;
static constexpr int R = 4;               // output rows per strip
static constexpr int NSTRIP = 256 / R;    // 64
static constexpr int NBC = 8 * 32;        // 256 images
static constexpr int MAXROWS = 2 * R + 7; // 15
static constexpr int SMEM_BYTES = MAXROWS * Wd * 4; // 30720

static constexpr unsigned FULL = 0xffffffffu;

__device__ __forceinline__ float2 f2_add(float2 a, float2 b) {
    return make_float2(a.x + b.x, a.y + b.y);
}
__device__ __forceinline__ float2 f2_fma(float k, float2 a, float2 b) {
    return make_float2(fmaf(k, a.x, b.x), fmaf(k, a.y, b.y));
}

__global__ __launch_bounds__(256, 4)
void lwt53_fused_kernel(const float* __restrict__ x, float* __restrict__ out) {
    extern __shared__ float A[];   // [nrows][512]; per row: s in [0,256), d in [256,512)

    const int blk   = blockIdx.x;
    const int strip = blk & (NSTRIP - 1);
    const int bc    = blk >> 6;            // log2(NSTRIP)=6
    const int r0    = strip * R;

    const int mlo   = max(0, 2 * r0 - 4);
    const int mhi   = min(H - 1, 2 * r0 + 2 * R + 2);
    const int nrows = mhi - mlo + 1;       // 11 (r0=0), 12 (r0=252), 15 interior

    const float* __restrict__ xim = x + (size_t)bc * (H * Wd) + (size_t)mlo * Wd;

    const int tid  = threadIdx.x;
    const int warp = tid >> 5;
    const int lane = tid & 31;
    const int lnm1 = (lane + 31) & 31;     // rotate-up source lane
    const int lnp1 = (lane + 1) & 31;      // rotate-down source lane

    // ================= Phase A: row lifting, pipelined + rotation shuffles ====
    {
        int rlist[2];
        int nr = 0;
        #pragma unroll
        for (int it = 0; it < 2; ++it) {
            const int r = warp + it * 8;
            if (r < nrows && !(r == 1 && r0 > 0)) rlist[nr++] = r;
        }

        float4 cur0, cur1, cur2, cur3;
        {
            const float4* __restrict__ xr =
                reinterpret_cast<const float4*>(xim + (size_t)rlist[0] * Wd);
            cur0 = xr[lane];  cur1 = xr[32 + lane];
            cur2 = xr[64 + lane]; cur3 = xr[96 + lane];
        }

        for (int i = 0; i < nr; ++i) {
            float4 nxt0, nxt1, nxt2, nxt3;
            const bool more = (i + 1 < nr);
            if (more) {
                const float4* __restrict__ xr =
                    reinterpret_cast<const float4*>(xim + (size_t)rlist[i + 1] * Wd);
                nxt0 = xr[lane];  nxt1 = xr[32 + lane];
                nxt2 = xr[64 + lane]; nxt3 = xr[96 + lane];
            }

            float eA[4] = {cur0.x, cur1.x, cur2.x, cur3.x};
            float oA[4] = {cur0.y, cur1.y, cur2.y, cur3.y};
            float eB[4] = {cur0.z, cur1.z, cur2.z, cur3.z};
            float oB[4] = {cur0.w, cur1.w, cur2.w, cur3.w};

            float dA[4], dB[4];
            #pragma unroll
            for (int j = 0; j < 4; j++) {
                const float srcP = (j > 0 && lane == 31) ? eB[j - 1] : eB[j];
                float Eprev = __shfl_sync(FULL, srcP, lnm1);
                if (j == 0) Eprev = (lane == 0) ? eB[0] : Eprev;      // refl i=0
                const float srcN = (j < 3 && lane == 0) ? eA[j + 1] : eA[j];
                float Enext = __shfl_sync(FULL, srcN, lnp1);
                if (j == 3) Enext = (lane == 31) ? eA[3] : Enext;     // refl i=255
                dA[j] = oA[j] - 0.5f * (Eprev + eB[j]);
                dB[j] = oB[j] - 0.5f * (eA[j] + Enext);
            }

            float* Arow = A + rlist[i] * Wd;
            float2* __restrict__ srow = reinterpret_cast<float2*>(Arow);
            float2* __restrict__ drow = reinterpret_cast<float2*>(Arow + 256);
            #pragma unroll
            for (int j = 0; j < 4; j++) {
                const float srcP = (j > 0 && lane == 31) ? dB[j - 1] : dB[j];
                float Dprev = __shfl_sync(FULL, srcP, lnm1);
                if (j == 0) Dprev = (lane == 0) ? dB[0] : Dprev;      // refl i=0
                const float srcN = (j < 3 && lane == 0) ? dA[j + 1] : dA[j];
                float Dnext = __shfl_sync(FULL, srcN, lnp1);
                if (j == 3) Dnext = (lane == 31) ? dA[3] : Dnext;     // refl i=255
                const float sA = eA[j] + 0.25f * (Dprev + dB[j]);
                const float sB = eB[j] + 0.25f * (dA[j] + Dnext);
                srow[32 * j + lane] = make_float2(sA, sB);
                drow[32 * j + lane] = make_float2(dA[j], dB[j]);
            }

            if (more) {
                cur0 = nxt0; cur1 = nxt1; cur2 = nxt2; cur3 = nxt3;
            }
        }
    }
    __syncthreads();

    // ============ Phase B: column lifting, 3-term sliding window ============
    // Thread owns a float2 column pair. t<128: s-columns (-> LL/LH);
    // t>=128: d-columns (-> HL/HH). Interior strips fully unrolled (6 iters).
    {
        const int t  = tid;
        const int cc = (t & 127) * 2;                   // coefficient column (even)
        const int sb = (t < 128) ? 0 : 256;             // smem half offset

        auto ldrow = [&](int j) -> float2 {             // E[j] column pair
            return *reinterpret_cast<const float2*>(
                A + (2 * j - mlo) * Wd + sb + cc);
        };
        auto ldodd = [&](int j) -> float2 {             // O[j] column pair
            return *reinterpret_cast<const float2*>(
                A + (2 * j + 1 - mlo) * Wd + sb + cc);
        };

        const int b = bc >> 5;
        const int c = bc & 31;
        float* __restrict__ base = out + ((size_t)b * 128 + c) * 65536;
        float* __restrict__ sOut = base + ((t < 128) ? (size_t)0 : 64 * 65536);
        float* __restrict__ dOut = base + ((t < 128) ? 32 * 65536 : 96 * 65536);

        if (r0 != 0 && r0 != 252) {
            // -------- interior strip: 6 iterations, fully unrolled --------
            // j = r0-1+q, q=0..5 ; no reflections possible.
            float2 eA = ldrow(r0 - 2);
            float2 eB = ldrow(r0 - 1);
            float2 Dm1 = make_float2(0.f, 0.f), Dm2 = make_float2(0.f, 0.f);

            #pragma unroll
            for (int q = 0; q < 6; ++q) {
                const int j = r0 - 1 + q;
                const float2 eC = ldrow(j + 1);
                const float2 O  = ldodd(j);

                const float2 D = f2_fma(-0.5f, f2_add(eA, eC), O);

                if (q >= 1 && q <= 4) {   // j in [r0, r0+3]
                    __stcs(reinterpret_cast<float2*>(dOut + (size_t)j * 256 + cc), D);
                }
                if (q >= 2) {             // S[j-1], j-1 in [r0, r0+3]
                    const float2 S = f2_fma(0.25f, f2_add(Dm2, D), eA);
                    __stcs(reinterpret_cast<float2*>(sOut + (size_t)(j - 1) * 256 + cc), S);
                }

                Dm2 = Dm1; Dm1 = D;
                eA = eB; eB = eC;
            }
        } else {
            // -------- edge strips: generic (verified) path --------
            const int jstart = (r0 == 0)   ? 0   : (r0 - 1);
            const int jend   = (r0 == 252) ? 255 : (r0 + R);

            float2 eA = ldrow((r0 == 0) ? 1 : (r0 - 2));
            float2 eB = ldrow(jstart);
            float2 Dm1 = make_float2(0.f, 0.f), Dm2 = make_float2(0.f, 0.f);

            for (int j = jstart; j <= jend; ++j) {
                const int jp = (j >= 255) ? 254 : (j + 1);
                const float2 eC = ldrow(jp);
                const float2 O  = ldodd(j);

                const float2 D = f2_fma(-0.5f, f2_add(eA, eC), O);

                if (j >= r0 && j <= r0 + R - 1) {
                    __stcs(reinterpret_cast<float2*>(dOut + (size_t)j * 256 + cc), D);
                }
                if (j >= r0 + 1) {
                    const float2 DA = (r0 == 0 && j == 1) ? D : Dm2;  // S[0] reflect
                    const float2 S = f2_fma(0.25f, f2_add(DA, D), eA);
                    __stcs(reinterpret_cast<float2*>(sOut + (size_t)(j - 1) * 256 + cc), S);
                }

                Dm2 = Dm1; Dm1 = D;
                eA = eB; eB = eC;
            }

            if (r0 == 252) {
                // S[255] = E[255] + 0.25*(2*D[254]); after final shift eA=E[255], Dm2=D[254]
                const float2 S = f2_fma(0.5f, Dm2, eA);
                __stcs(reinterpret_cast<float2*>(sOut + (size_t)255 * 256 + cc), S);
            }
        }
    }
}

extern "C" void kernel_launch(void* const* d_in, const int* in_sizes, int n_in,
                              void* d_out, int out_size) {
    const float* x = (const float*)d_in[0];
    float* out = (float*)d_out;
    (void)in_sizes; (void)n_in; (void)out_size;

    static bool attr_set = false;
    if (!attr_set) {
        cudaFuncSetAttribute(lwt53_fused_kernel,
                             cudaFuncAttributeMaxDynamicSharedMemorySize, SMEM_BYTES);
        attr_set = true;
    }

    dim3 grid(NBC * NSTRIP);   // 16384
    dim3 block(256);
    lwt53_fused_kernel<<<grid, block, SMEM_BYTES>>>(x, out);
}

// round 17
// speedup vs baseline: 1.0273x; 1.0273x over previous
#include <cuda_runtime.h>
#include <cstdint>

// Forward 5/3 lifting wavelet, 2D separable, fused tile kernel.
// x: (8, 32, 512, 512) f32 -> out: (8, 128, 256, 256) f32
// out channels: [LL(0:32) | LH(32:64) | HL(64:96) | HH(96:128)]
//
//   d[i] = odd[i] - 0.5*(even[il] + even[ir]), il=(i==0)?1:i-1, ir=(i==255)?254:i+1
//   s[i] = even[i] + 0.25*(d[il] + d[ir])     (same reflected indices)
//
// R=16 rows/strip (39-row tile, 78KB smem), 512-thread CTAs, 2 CTAs/SM.
// Rationale: halo read amplification drops 1.44x -> 1.22x vs R=8; per-warp
// MLP is supplied by the software-pipelined Phase A (R13), so the reduced
// phase-machine count should no longer dominate. Phase B: each 256-thread
// half owns 8 output rows and runs the verified unrolled recurrence.

static constexpr int H = 512;
static constexpr int Wd = 512;
static constexpr int R = 16;              // output rows per strip
static constexpr int NSTRIP = 256 / R;    // 16
static constexpr int NBC = 8 * 32;        // 256 images
static constexpr int MAXROWS = 2 * R + 7; // 39
static constexpr int SMEM_BYTES = MAXROWS * Wd * 4; // 79872

static constexpr unsigned FULL = 0xffffffffu;

__device__ __forceinline__ float2 f2_add(float2 a, float2 b) {
    return make_float2(a.x + b.x, a.y + b.y);
}
__device__ __forceinline__ float2 f2_fma(float k, float2 a, float2 b) {
    return make_float2(fmaf(k, a.x, b.x), fmaf(k, a.y, b.y));
}

__global__ __launch_bounds__(512, 2)
void lwt53_fused_kernel(const float* __restrict__ x, float* __restrict__ out) {
    extern __shared__ float A[];   // [nrows][512]; per row: s in [0,256), d in [256,512)

    const int blk   = blockIdx.x;
    const int strip = blk & (NSTRIP - 1);
    const int bc    = blk >> 4;            // log2(NSTRIP)=4
    const int r0    = strip * R;

    const int mlo   = max(0, 2 * r0 - 4);
    const int mhi   = min(H - 1, 2 * r0 + 2 * R + 2);
    const int nrows = mhi - mlo + 1;       // 35 (r0=0), 36 (r0=240), 39 interior

    const float* __restrict__ xim = x + (size_t)bc * (H * Wd) + (size_t)mlo * Wd;

    const int tid  = threadIdx.x;
    const int warp = tid >> 5;             // 0..15
    const int lane = tid & 31;
    const int lnm1 = (lane + 31) & 31;     // rotate-up source lane
    const int lnp1 = (lane + 1) & 31;      // rotate-down source lane

    // ================= Phase A: row lifting, pipelined + rotation shuffles ====
    {
        int rlist[3];
        int nr = 0;
        #pragma unroll
        for (int it = 0; it < 3; ++it) {
            const int r = warp + it * 16;
            if (r < nrows && !(r == 1 && r0 > 0)) rlist[nr++] = r;
        }

        float4 cur0, cur1, cur2, cur3;
        {
            const float4* __restrict__ xr =
                reinterpret_cast<const float4*>(xim + (size_t)rlist[0] * Wd);
            cur0 = xr[lane];  cur1 = xr[32 + lane];
            cur2 = xr[64 + lane]; cur3 = xr[96 + lane];
        }

        for (int i = 0; i < nr; ++i) {
            float4 nxt0, nxt1, nxt2, nxt3;
            const bool more = (i + 1 < nr);
            if (more) {
                const float4* __restrict__ xr =
                    reinterpret_cast<const float4*>(xim + (size_t)rlist[i + 1] * Wd);
                nxt0 = xr[lane];  nxt1 = xr[32 + lane];
                nxt2 = xr[64 + lane]; nxt3 = xr[96 + lane];
            }

            float eA[4] = {cur0.x, cur1.x, cur2.x, cur3.x};
            float oA[4] = {cur0.y, cur1.y, cur2.y, cur3.y};
            float eB[4] = {cur0.z, cur1.z, cur2.z, cur3.z};
            float oB[4] = {cur0.w, cur1.w, cur2.w, cur3.w};

            float dA[4], dB[4];
            #pragma unroll
            for (int j = 0; j < 4; j++) {
                const float srcP = (j > 0 && lane == 31) ? eB[j - 1] : eB[j];
                float Eprev = __shfl_sync(FULL, srcP, lnm1);
                if (j == 0) Eprev = (lane == 0) ? eB[0] : Eprev;      // refl i=0
                const float srcN = (j < 3 && lane == 0) ? eA[j + 1] : eA[j];
                float Enext = __shfl_sync(FULL, srcN, lnp1);
                if (j == 3) Enext = (lane == 31) ? eA[3] : Enext;     // refl i=255
                dA[j] = oA[j] - 0.5f * (Eprev + eB[j]);
                dB[j] = oB[j] - 0.5f * (eA[j] + Enext);
            }

            float* Arow = A + rlist[i] * Wd;
            float2* __restrict__ srow = reinterpret_cast<float2*>(Arow);
            float2* __restrict__ drow = reinterpret_cast<float2*>(Arow + 256);
            #pragma unroll
            for (int j = 0; j < 4; j++) {
                const float srcP = (j > 0 && lane == 31) ? dB[j - 1] : dB[j];
                float Dprev = __shfl_sync(FULL, srcP, lnm1);
                if (j == 0) Dprev = (lane == 0) ? dB[0] : Dprev;      // refl i=0
                const float srcN = (j < 3 && lane == 0) ? dA[j + 1] : dA[j];
                float Dnext = __shfl_sync(FULL, srcN, lnp1);
                if (j == 3) Dnext = (lane == 31) ? dA[3] : Dnext;     // refl i=255
                const float sA = eA[j] + 0.25f * (Dprev + dB[j]);
                const float sB = eB[j] + 0.25f * (dA[j] + Dnext);
                srow[32 * j + lane] = make_float2(sA, sB);
                drow[32 * j + lane] = make_float2(dA[j], dB[j]);
            }

            if (more) {
                cur0 = nxt0; cur1 = nxt1; cur2 = nxt2; cur3 = nxt3;
            }
        }
    }
    __syncthreads();

    // ============ Phase B: column lifting, 3-term sliding window ============
    // 512 threads = 2 halves of 256. Half h owns output rows r0h..r0h+7 with
    // r0h = r0 + 8h. Within a half: pt<128 -> s-columns (LL/LH), pt>=128 ->
    // d-columns (HL/HH), float2 column pair each. Same verified recurrence.
    {
        const int pt   = tid & 255;
        const int half = tid >> 8;
        const int r0h  = r0 + 8 * half;
        const int cc = (pt & 127) * 2;                  // coefficient column (even)
        const int sb = (pt < 128) ? 0 : 256;            // smem half offset

        auto ldrow = [&](int j) -> float2 {             // E[j] column pair
            return *reinterpret_cast<const float2*>(
                A + (2 * j - mlo) * Wd + sb + cc);
        };
        auto ldodd = [&](int j) -> float2 {             // O[j] column pair
            return *reinterpret_cast<const float2*>(
                A + (2 * j + 1 - mlo) * Wd + sb + cc);
        };

        const int b = bc >> 5;
        const int c = bc & 31;
        float* __restrict__ base = out + ((size_t)b * 128 + c) * 65536;
        float* __restrict__ sOut = base + ((pt < 128) ? (size_t)0 : 64 * 65536);
        float* __restrict__ dOut = base + ((pt < 128) ? 32 * 65536 : 96 * 65536);

        if (r0h != 0 && r0h != 248) {
            // -------- interior half: 10 iterations, fully unrolled --------
            float2 eA = ldrow(r0h - 2);
            float2 eB = ldrow(r0h - 1);
            float2 Dm1 = make_float2(0.f, 0.f), Dm2 = make_float2(0.f, 0.f);

            #pragma unroll
            for (int q = 0; q < 10; ++q) {
                const int j = r0h - 1 + q;
                const float2 eC = ldrow(j + 1);
                const float2 O  = ldodd(j);

                const float2 D = f2_fma(-0.5f, f2_add(eA, eC), O);

                if (q >= 1 && q <= 8) {   // j in [r0h, r0h+7]
                    __stcs(reinterpret_cast<float2*>(dOut + (size_t)j * 256 + cc), D);
                }
                if (q >= 2) {             // S[j-1], j-1 in [r0h, r0h+7]
                    const float2 S = f2_fma(0.25f, f2_add(Dm2, D), eA);
                    __stcs(reinterpret_cast<float2*>(sOut + (size_t)(j - 1) * 256 + cc), S);
                }

                Dm2 = Dm1; Dm1 = D;
                eA = eB; eB = eC;
            }
        } else {
            // -------- edge halves (r0h==0 or r0h==248): generic path --------
            const int jstart = (r0h == 0)   ? 0   : (r0h - 1);
            const int jend   = (r0h == 248) ? 255 : (r0h + 8);

            float2 eA = ldrow((r0h == 0) ? 1 : (r0h - 2));
            float2 eB = ldrow(jstart);
            float2 Dm1 = make_float2(0.f, 0.f), Dm2 = make_float2(0.f, 0.f);

            for (int j = jstart; j <= jend; ++j) {
                const int jp = (j >= 255) ? 254 : (j + 1);
                const float2 eC = ldrow(jp);
                const float2 O  = ldodd(j);

                const float2 D = f2_fma(-0.5f, f2_add(eA, eC), O);

                if (j >= r0h && j <= r0h + 7) {
                    __stcs(reinterpret_cast<float2*>(dOut + (size_t)j * 256 + cc), D);
                }
                if (j >= r0h + 1) {
                    const float2 DA = (r0h == 0 && j == 1) ? D : Dm2;  // S[0] reflect
                    const float2 S = f2_fma(0.25f, f2_add(DA, D), eA);
                    __stcs(reinterpret_cast<float2*>(sOut + (size_t)(j - 1) * 256 + cc), S);
                }

                Dm2 = Dm1; Dm1 = D;
                eA = eB; eB = eC;
            }

            if (r0h == 248) {
                // S[255] = E[255] + 0.25*(2*D[254]); after final shift eA=E[255], Dm2=D[254]
                const float2 S = f2_fma(0.5f, Dm2, eA);
                __stcs(reinterpret_cast<float2*>(sOut + (size_t)255 * 256 + cc), S);
            }
        }
    }
}

extern "C" void kernel_launch(void* const* d_in, const int* in_sizes, int n_in,
                              void* d_out, int out_size) {
    const float* x = (const float*)d_in[0];
    float* out = (float*)d_out;
    (void)in_sizes; (void)n_in; (void)out_size;

    static bool attr_set = false;
    if (!attr_set) {
        cudaFuncSetAttribute(lwt53_fused_kernel,
                             cudaFuncAttributeMaxDynamicSharedMemorySize, SMEM_BYTES);
        attr_set = true;
    }

    dim3 grid(NBC * NSTRIP);   // 4096
    dim3 block(512);
    lwt53_fused_kernel<<<grid, block, SMEM_BYTES>>>(x, out);
}